// round 5
// baseline (speedup 1.0000x reference)
#include <cuda_runtime.h>
#include <math.h>
#include <stdint.h>

#define KP 32      // particles
#define BB 256     // batch
#define TT 32      // time steps
#define DH 128
#define EH 128

typedef unsigned long long ull;

// ---------------- scratch (device globals; no allocation) ----------------
__device__ float g_E1[BB * TT * EH];          // enc @ W1_e + b1
__device__ float g_H[2][KP * BB * DH];        // ping-pong hiddens
__device__ float g_C[2][KP * BB * DH];        // ping-pong cells
__device__ float g_yt[BB];                    // y_tilde (F=1)
__device__ float g_spF[BB * DH];              // softplus(var), full width
__device__ float g_ctx[BB * EH];              // context (last step used at end)
__device__ float g_projP[2][KP * BB];         // h2.fcdW partial per d-half
__device__ float g_pdfP[2][KP * BB];          // h2.pdfW partial per d-half
__device__ int   g_srcH[KP * BB];             // composed resample index for h
__device__ int   g_srcC[KP * BB];             // resample index for c (unsorted!)
__device__ unsigned g_flag[BB];               // attention-done flag (monotonic t+1)

__device__ __forceinline__ float sigm(float x) { return 1.0f / (1.0f + expf(-x)); }
__device__ __forceinline__ float softplusf(float x) {
    return fmaxf(x, 0.0f) + log1pf(expf(-fabsf(x)));
}
__device__ __forceinline__ void fma2(ull& d, ull a, ull b) {
    asm("fma.rn.f32x2 %0, %1, %2, %0;" : "+l"(d) : "l"(a), "l"(b));
}
__device__ __forceinline__ float2 unpk(ull v) {
    float2 f; asm("mov.b64 {%0,%1}, %2;" : "=f"(f.x), "=f"(f.y) : "l"(v)); return f;
}
__device__ __forceinline__ ull pk(float lo, float hi) {
    ull u; asm("mov.b64 %0, {%1,%2};" : "=l"(u) : "f"(lo), "f"(hi)); return u;
}
__device__ __forceinline__ uint32_t s2u32(const void* p) {
    uint32_t a;
    asm("{ .reg .u64 t; cvta.to.shared.u64 t, %1; cvt.u32.u64 %0, t; }" : "=r"(a) : "l"(p));
    return a;
}
__device__ __forceinline__ void cp16(uint32_t dst, const void* src) {
    asm volatile("cp.async.ca.shared.global [%0], [%1], 16;" :: "r"(dst), "l"(src));
}
#define CP_COMMIT() asm volatile("cp.async.commit_group;")
#define CP_WAIT0()  asm volatile("cp.async.wait_group 0;")
#define CP_WAIT1()  asm volatile("cp.async.wait_group 1;")

// ---------------- dynamic smem layout for kA ------------------------------
struct __align__(16) SmemA {
    float ws[2][8 * 256];      // 16KB : W_hh chunk double buffer (8 rows x d-half cols)
    ull   h2[KP * 128];        // 32KB : (h,h) duplicated pairs, k-major [k][j]
    float hbar[DH], cbar[DH], hcp[DH], hcp2[DH], sp[DH];
    float a_s[TT], beta_s[TT], ctx_s[EH];
    float yt;
};

// ---------------- K0: E1 precompute + flag reset ---------------------------
__global__ void k0_e1(const float* __restrict__ enc, const float* __restrict__ W1,
                      const float* __restrict__ b1)
{
    int b = blockIdx.x, tid = threadIdx.x;
    __shared__ float enc_s[TT * EH];
    __shared__ float w1_s[16 * 128];
    if (tid == 0) g_flag[b] = 0u;       // reset producer flags for this replay
    for (int idx = tid; idx < TT * EH; idx += 256)
        enc_s[idx] = enc[b * TT * EH + idx];
    int tq = tid >> 7;
    int h  = tid & 127;
    float acc[16];
#pragma unroll
    for (int i = 0; i < 16; i++) acc[i] = 0.0f;
    for (int ec = 0; ec < 8; ec++) {
        __syncthreads();
        for (int idx = tid; idx < 16 * 128; idx += 256)
            w1_s[idx] = W1[(256 + ec * 16) * 128 + idx];
        __syncthreads();
#pragma unroll 4
        for (int jj = 0; jj < 16; jj++) {
            float wv = w1_s[jj * 128 + h];
            int e = ec * 16 + jj;
#pragma unroll
            for (int i = 0; i < 16; i++)
                acc[i] += enc_s[(tq * 16 + i) * 128 + e] * wv;
        }
    }
    float bv = b1[h];
#pragma unroll
    for (int i = 0; i < 16; i++)
        g_E1[(b * TT + tq * 16 + i) * 128 + h] = acc[i] + bv;
}

// ---------------- kA: attention (dh=0 only) + LSTM half -------------------
// grid = 512: blockIdx.x = b*2 + dhalf. dh=0 computes attention and publishes
// yt/sp via flag; dh=1 overlaps its GEMM with that and spins before epilogue.
__global__ void __launch_bounds__(256, 4) kA_step(
        int t, const float* __restrict__ enc, const float* __restrict__ yprev,
        const float* __restrict__ W1, const float* __restrict__ W2,
        const float* __restrict__ b2, const float* __restrict__ fcW,
        const float* __restrict__ fcb, const float* __restrict__ varW,
        const float* __restrict__ varb,
        const float* __restrict__ Whh, const float* __restrict__ Wih,
        const float* __restrict__ bih, const float* __restrict__ bhh,
        const float* __restrict__ eps,
        const float* __restrict__ fcdW, const float* __restrict__ pdfW)
{
    extern __shared__ char smem_raw[];
    SmemA* S = (SmemA*)smem_raw;
    int bid = blockIdx.x;
    int b = bid >> 1, dh = bid & 1;
    int tid = threadIdx.x;
    int rb = (t - 1) & 1, wb = t & 1;
    int dhoff = dh * 64;   // global d offset of this CTA's half

    // ---- cp.async prologue: W_hh chunks 0,1 ----
    if (t > 0) {
#pragma unroll
        for (int c0 = 0; c0 < 2; c0++) {
            uint32_t dstb = s2u32(&S->ws[c0][0]);
#pragma unroll
            for (int n = 0; n < 2; n++) {
                int L = tid + n * 256;           // 0..511 lines of 16B
                int row = L >> 6, rem = L & 63;
                int seg = rem >> 4, q = rem & 15;
                const float* src = Whh + (c0 * 8 + row) * 512 + seg * 128 + dhoff + q * 4;
                cp16(dstb + (row * 256 + seg * 64 + q * 4) * 4, src);
            }
            CP_COMMIT();
        }
        // fill h2[k][j] = (h,h) via resample gather
        for (int m = 0; m < 16; m++) {
            int idx = tid + m * 256;
            int k = idx >> 7, j = idx & 127;
            int row = g_srcH[k * BB + b];
            float hv = g_H[rb][(row * BB + b) * DH + j];
            S->h2[k * 128 + j] = pk(hv, hv);
        }
    }
    __syncthreads();

    int w = tid >> 5, lane = tid & 31;

    // =========== dh==0 : full attention chain + publish ===========
    if (dh == 0) {
        // hbar from smem h2 (lo words); cbar from global gather
        if (tid < 128) {
            float s0 = 0.0f, s1 = 0.0f;
            if (t > 0) {
                const float* hp = (const float*)S->h2;
#pragma unroll
                for (int p = 0; p < KP; p += 2) {
                    s0 += hp[(p * 128 + tid) * 2];
                    s1 += hp[((p + 1) * 128 + tid) * 2];
                }
            }
            S->hbar[tid] = (s0 + s1) * (1.0f / 32.0f);
        } else {
            int d = tid - 128;
            float s = 0.0f;
            if (t > 0)
                for (int p = 0; p < KP; p++) {
                    int row = g_srcC[p * BB + b];
                    s += g_C[rb][(row * BB + b) * DH + d];
                }
            S->cbar[d] = s * (1.0f / 32.0f);
        }
        __syncthreads();

        // hc_proj = hbar@W1_h + cbar@W1_c  (4-acc dots)
        if (tid < 128) {
            float a0 = 0, a1 = 0, a2 = 0, a3 = 0;
#pragma unroll 4
            for (int j = 0; j < 32; j++) {
                a0 += S->hbar[j]      * W1[j * 128 + tid];
                a1 += S->hbar[j + 32] * W1[(j + 32) * 128 + tid];
                a2 += S->hbar[j + 64] * W1[(j + 64) * 128 + tid];
                a3 += S->hbar[j + 96] * W1[(j + 96) * 128 + tid];
            }
            S->hcp[tid] = (a0 + a1) + (a2 + a3);
        } else {
            int h = tid - 128;
            float a0 = 0, a1 = 0, a2 = 0, a3 = 0;
#pragma unroll 4
            for (int j = 0; j < 32; j++) {
                a0 += S->cbar[j]      * W1[(128 + j) * 128 + h];
                a1 += S->cbar[j + 32] * W1[(160 + j) * 128 + h];
                a2 += S->cbar[j + 64] * W1[(192 + j) * 128 + h];
                a3 += S->cbar[j + 96] * W1[(224 + j) * 128 + h];
            }
            S->hcp2[h] = (a0 + a1) + (a2 + a3);
        }
        __syncthreads();
        if (tid < 128) S->hcp[tid] += S->hcp2[tid];
        __syncthreads();

        // attention logits
#pragma unroll
        for (int q = 0; q < 4; q++) {
            int tp = w * 4 + q;
            const float* e1 = &g_E1[(b * TT + tp) * 128];
            float acc = 0.0f;
            for (int hh = lane; hh < 128; hh += 32)
                acc += tanhf(S->hcp[hh] + e1[hh]) * W2[hh];
            for (int off = 16; off; off >>= 1) acc += __shfl_down_sync(0xffffffffu, acc, off);
            if (lane == 0) S->a_s[tp] = acc + b2[0];
        }
        __syncthreads();

        // softmax over T
        if (w == 0) {
            float v = S->a_s[lane];
            float m = v;
            for (int off = 16; off; off >>= 1) m = fmaxf(m, __shfl_xor_sync(0xffffffffu, m, off));
            float e = expf(v - m);
            float s = e;
            for (int off = 16; off; off >>= 1) s += __shfl_xor_sync(0xffffffffu, s, off);
            S->beta_s[lane] = e / s;
        }
        __syncthreads();

        // context (4-acc)
        if (tid < 128) {
            float a0 = 0, a1 = 0, a2 = 0, a3 = 0;
#pragma unroll 4
            for (int tp = 0; tp < 8; tp++) {
                a0 += S->beta_s[tp]      * enc[(b * TT + tp) * 128 + tid];
                a1 += S->beta_s[tp + 8]  * enc[(b * TT + tp + 8) * 128 + tid];
                a2 += S->beta_s[tp + 16] * enc[(b * TT + tp + 16) * 128 + tid];
                a3 += S->beta_s[tp + 24] * enc[(b * TT + tp + 24) * 128 + tid];
            }
            float acc = (a0 + a1) + (a2 + a3);
            S->ctx_s[tid] = acc;
            g_ctx[b * 128 + tid] = acc;
        }
        __syncthreads();

        // y_tilde (scalar)
        if (w == 0) {
            float acc = 0.0f;
            for (int e = lane; e < 128; e += 32) acc += S->ctx_s[e] * fcW[e];
            for (int off = 16; off; off >>= 1) acc += __shfl_down_sync(0xffffffffu, acc, off);
            if (lane == 0) {
                float yt = acc + yprev[b * TT + t] * fcW[128] + fcb[0];
                S->yt = yt;
                g_yt[b] = yt;
            }
        }
        __syncthreads();

        // var full width -> softplus, publish (4-acc)
        if (tid < 128) {
            float a0 = 0, a1 = 0, a2 = 0, a3 = 0;
#pragma unroll 4
            for (int j = 0; j < 32; j++) {
                a0 += S->hbar[j]      * varW[(1 + j) * 128 + tid];
                a1 += S->hbar[j + 32] * varW[(33 + j) * 128 + tid];
                a2 += S->hbar[j + 64] * varW[(65 + j) * 128 + tid];
                a3 += S->hbar[j + 96] * varW[(97 + j) * 128 + tid];
            }
            float v = (a0 + a1) + (a2 + a3) + S->yt * varW[tid] + varb[tid];
            float sp = softplusf(v);
            S->sp[tid] = sp;
            g_spF[b * 128 + tid] = sp;
            __threadfence();   // make sp/yt/ctx visible device-wide
        }
        __syncthreads();
        if (tid == 0) atomicExch(&g_flag[b], (unsigned)(t + 1));   // release
    }

    // =========== phase 2: LSTM GEMM (both halves) ===========
    int kg  = tid >> 5;        // 0..7 : 4 particles each; one warp per kg
    int dqh = tid & 31;        // d-pair within half
    int d0l = dqh * 2;
    int d0g = dhoff + d0l;

    ull acc2[4][4];
#pragma unroll
    for (int i = 0; i < 4; i++)
#pragma unroll
        for (int g = 0; g < 4; g++) acc2[i][g] = 0ull;

    if (t > 0) {
        for (int ch = 0; ch < 16; ch++) {
            if (ch < 15) { CP_WAIT1(); } else { CP_WAIT0(); }
            __syncthreads();
            const float* wsb = S->ws[ch & 1];
#pragma unroll
            for (int jj = 0; jj < 8; jj++) {
                int j = ch * 8 + jj;
                ull h0 = S->h2[(kg * 4 + 0) * 128 + j];
                ull h1 = S->h2[(kg * 4 + 1) * 128 + j];
                ull h2v = S->h2[(kg * 4 + 2) * 128 + j];
                ull h3 = S->h2[(kg * 4 + 3) * 128 + j];
                const ull* wp = (const ull*)(wsb + jj * 256);
                ull w0 = wp[dqh], w1 = wp[32 + dqh], w2 = wp[64 + dqh], w3 = wp[96 + dqh];
                fma2(acc2[0][0], h0, w0); fma2(acc2[0][1], h0, w1);
                fma2(acc2[0][2], h0, w2); fma2(acc2[0][3], h0, w3);
                fma2(acc2[1][0], h1, w0); fma2(acc2[1][1], h1, w1);
                fma2(acc2[1][2], h1, w2); fma2(acc2[1][3], h1, w3);
                fma2(acc2[2][0], h2v, w0); fma2(acc2[2][1], h2v, w1);
                fma2(acc2[2][2], h2v, w2); fma2(acc2[2][3], h2v, w3);
                fma2(acc2[3][0], h3, w0); fma2(acc2[3][1], h3, w1);
                fma2(acc2[3][2], h3, w2); fma2(acc2[3][3], h3, w3);
            }
            __syncthreads();
            if (ch + 2 < 16) {
                uint32_t dstb = s2u32(&S->ws[ch & 1][0]);
#pragma unroll
                for (int n = 0; n < 2; n++) {
                    int L = tid + n * 256;
                    int row = L >> 6, rem = L & 63;
                    int seg = rem >> 4, q = rem & 15;
                    const float* src = Whh + ((ch + 2) * 8 + row) * 512 + seg * 128 + dhoff + q * 4;
                    cp16(dstb + (row * 256 + seg * 64 + q * 4) * 4, src);
                }
                CP_COMMIT();
            }
        }
    }

    // dh==1: wait for attention results
    if (dh == 1) {
        if (tid == 0) {
            while (atomicAdd(&g_flag[b], 0u) < (unsigned)(t + 1)) { }
        }
        __syncthreads();   // all threads' loads of yt/sp below ordered after this
    }

    // ---- epilogue: gates -> c2/h2, reparam, dots ----
    float yt = (dh == 0) ? S->yt : g_yt[b];
    float2 spv;
    if (dh == 0) spv = *(const float2*)&S->sp[d0g];
    else         spv = *(const float2*)&g_spF[b * 128 + d0g];

    float xb[8];
#pragma unroll
    for (int g4 = 0; g4 < 4; g4++)
#pragma unroll
        for (int dd = 0; dd < 2; dd++) {
            int col = g4 * 128 + d0g + dd;
            xb[g4 * 2 + dd] = yt * Wih[col] + bih[col] + bhh[col];
        }

    float fcd0 = fcdW[d0g], fcd1 = fcdW[d0g + 1];
    float pw0 = pdfW[d0g],  pw1 = pdfW[d0g + 1];
    float pacc[4], qacc[4];
#pragma unroll
    for (int i = 0; i < 4; i++) {
        int k = kg * 4 + i;
        float2 gi = unpk(acc2[i][0]);
        float2 gf = unpk(acc2[i][1]);
        float2 gg = unpk(acc2[i][2]);
        float2 go = unpk(acc2[i][3]);
        float cp0 = 0.0f, cp1 = 0.0f;
        if (t > 0) {
            int crow = g_srcC[k * BB + b];
            float2 cv = *(const float2*)&g_C[rb][(crow * BB + b) * DH + d0g];
            cp0 = cv.x; cp1 = cv.y;
        }
        float ii0 = gi.x + xb[0], ii1 = gi.y + xb[1];
        float ff0 = gf.x + xb[2], ff1 = gf.y + xb[3];
        float gg0 = gg.x + xb[4], gg1 = gg.y + xb[5];
        float oo0 = go.x + xb[6], oo1 = go.y + xb[7];
        float c20 = sigm(ff0) * cp0 + sigm(ii0) * tanhf(gg0);
        float c21 = sigm(ff1) * cp1 + sigm(ii1) * tanhf(gg1);
        float h20 = sigm(oo0) * tanhf(c20);
        float h21 = sigm(oo1) * tanhf(c21);
        float2 ev = *(const float2*)&eps[(((size_t)t * KP + k) * BB + b) * DH + d0g];
        h20 += ev.x * spv.x;
        h21 += ev.y * spv.y;
        int o = (k * BB + b) * DH + d0g;
        *(float2*)&g_H[wb][o] = make_float2(h20, h21);
        *(float2*)&g_C[wb][o] = make_float2(c20, c21);
        pacc[i] = h20 * fcd0 + h21 * fcd1;
        qacc[i] = h20 * pw0 + h21 * pw1;
    }
#pragma unroll
    for (int i = 0; i < 4; i++) {
        float p = pacc[i], q = qacc[i];
        for (int off = 16; off; off >>= 1) {
            p += __shfl_down_sync(0xffffffffu, p, off);
            q += __shfl_down_sync(0xffffffffu, q, off);
        }
        if (dqh == 0) {
            int k = kg * 4 + i;
            g_projP[dh][k * BB + b] = p;
            g_pdfP[dh][k * BB + b] = q;
        }
    }
}

// ---------------- K3: sort / weights / gumbel-max resample ----------------
__global__ void __launch_bounds__(1024) k3_resample(
        int t, const float* __restrict__ gumbel,
        const float* __restrict__ pdfW, const float* __restrict__ pdfb,
        const float* __restrict__ fcdb)
{
    int blk = blockIdx.x;          // 0..7 (32-b normalization groups)
    int tid = threadIdx.x;         // 1024
    __shared__ float proj_s[32][33];
    __shared__ int   order_s[32][33];
    __shared__ float pd_s[32][33];  // pdfdot transposed
    __shared__ float lw_s[32][33];  // [b_local][slot]

    {   // assemble proj = half0 + half1 + fcdb; store transposed
        int kk = tid >> 5, bb = tid & 31;
        int gi = kk * BB + blk * 32 + bb;
        proj_s[bb][kk] = g_projP[0][gi] + g_projP[1][gi] + fcdb[0];
        pd_s[bb][kk]   = g_pdfP[0][gi] + g_pdfP[1][gi];
    }
    __syncthreads();
    {   // stable ascending rank (matches jnp.argsort)
        int bl = tid >> 5, k = tid & 31;
        float v = proj_s[bl][k];
        int r = 0;
#pragma unroll
        for (int kp = 0; kp < 32; kp++) {
            float u = proj_s[bl][kp];
            r += (u < v) || (u == v && kp < k);
        }
        order_s[bl][r] = k;
    }
    __syncthreads();
    {   // weights per slot, normalized over the 32-b block; lw = log(w+1e-30)
        int slot = tid >> 5, bb = tid & 31;
        int bg = blk * 32 + bb;
        int k0 = order_s[bb][slot];
        float lp = pd_s[bb][k0] + g_yt[bg] * pdfW[128] + pdfb[0];
        float v = expf(lp);
        float s = v;
        for (int off = 16; off; off >>= 1) s += __shfl_xor_sync(0xffffffffu, s, off);
        lw_s[bb][slot] = logf(v / s + 1e-30f);
    }
    __syncthreads();
    {   // gumbel argmax: warp handles p = warp_id; prefetch all 32 rows
        int p = tid >> 5, lane = tid & 31;
        const float* gbase = &gumbel[(((size_t)t * BB + blk * 32) * KP + p) * KP + lane];
        float gv[32];
#pragma unroll
        for (int it = 0; it < 32; it++)
            gv[it] = gbase[(size_t)it * KP * KP];
#pragma unroll
        for (int it = 0; it < 32; it++) {
            float v = lw_s[it][lane] + gv[it];
            int bi = lane;
            for (int off = 16; off; off >>= 1) {
                float ov = __shfl_down_sync(0xffffffffu, v, off);
                int  obi = __shfl_down_sync(0xffffffffu, bi, off);
                if (ov > v || (ov == v && obi < bi)) { v = ov; bi = obi; }
            }
            if (lane == 0) {
                int bg = blk * 32 + it;
                g_srcH[p * BB + bg] = order_s[it][bi];  // h sorted before selection
                g_srcC[p * BB + bg] = bi;               // c NOT sorted (torch quirk)
            }
        }
    }
}

// ---------------- K4: final projections -----------------------------------
__global__ void k4_out(const float* __restrict__ fcdW, const float* __restrict__ fcdb,
                       const float* __restrict__ fceW, const float* __restrict__ fceb,
                       float* __restrict__ out)
{
    int b = blockIdx.x * 8 + (threadIdx.x >> 5);
    int lane = threadIdx.x & 31;
    float a1 = 0.0f, a2 = 0.0f;
    for (int d = lane; d < 128; d += 32) {
        float hm = 0.0f;
        for (int p = 0; p < KP; p++) {
            int row = g_srcH[p * BB + b];
            hm += g_H[1][(row * BB + b) * DH + d];   // (T-1)&1 == 1
        }
        a1 += (hm * (1.0f / 32.0f)) * fcdW[d];
        a2 += g_ctx[b * 128 + d] * fceW[d];
    }
    for (int off = 16; off; off >>= 1) {
        a1 += __shfl_down_sync(0xffffffffu, a1, off);
        a2 += __shfl_down_sync(0xffffffffu, a2, off);
    }
    if (lane == 0) out[b] = a1 + fcdb[0] + a2 + fceb[0];
}

// ---------------- launch ---------------------------------------------------
extern "C" void kernel_launch(void* const* d_in, const int* in_sizes, int n_in,
                              void* d_out, int out_size)
{
    const float* enc   = (const float*)d_in[0];
    const float* yprev = (const float*)d_in[1];
    const float* eps   = (const float*)d_in[2];
    const float* gum   = (const float*)d_in[3];
    const float* W1    = (const float*)d_in[4];
    const float* b1    = (const float*)d_in[5];
    const float* W2    = (const float*)d_in[6];
    const float* b2    = (const float*)d_in[7];
    const float* Wih   = (const float*)d_in[8];
    const float* Whh   = (const float*)d_in[9];
    const float* bih   = (const float*)d_in[10];
    const float* bhh   = (const float*)d_in[11];
    const float* fcW   = (const float*)d_in[12];
    const float* fcb   = (const float*)d_in[13];
    const float* fcdW  = (const float*)d_in[14];
    const float* fcdb  = (const float*)d_in[15];
    const float* fceW  = (const float*)d_in[16];
    const float* fceb  = (const float*)d_in[17];
    const float* varW  = (const float*)d_in[18];
    const float* varb  = (const float*)d_in[19];
    const float* pdfW  = (const float*)d_in[20];
    const float* pdfb  = (const float*)d_in[21];
    float* out = (float*)d_out;

    const int SMEM_BYTES = (int)sizeof(SmemA);
    cudaFuncSetAttribute(kA_step, cudaFuncAttributeMaxDynamicSharedMemorySize, SMEM_BYTES);

    k0_e1<<<BB, 256>>>(enc, W1, b1);
    for (int t = 0; t < TT; t++) {
        kA_step<<<BB * 2, 256, SMEM_BYTES>>>(t, enc, yprev, W1, W2, b2, fcW, fcb,
                                             varW, varb, Whh, Wih, bih, bhh, eps,
                                             fcdW, pdfW);
        k3_resample<<<8, 1024>>>(t, gum, pdfW, pdfb, fcdb);
    }
    k4_out<<<BB / 8, 256>>>(fcdW, fcdb, fceW, fceb, out);
}

// round 6
// speedup vs baseline: 1.1619x; 1.1619x over previous
#include <cuda_runtime.h>
#include <math.h>
#include <stdint.h>

#define KP 32      // particles
#define BB 256     // batch
#define TT 32      // time steps
#define DH 128
#define EH 128

typedef unsigned long long ull;

// ---------------- scratch (device globals; no allocation) ----------------
__device__ float g_E1[BB * TT * EH];          // enc @ W1_e + b1
__device__ float g_H[2][KP * BB * DH];        // ping-pong hiddens
__device__ float g_C[2][KP * BB * DH];        // ping-pong cells
__device__ float g_yt[BB];                    // y_tilde (F=1)
__device__ float g_spF[BB * DH];              // softplus(var)
__device__ float g_ctx[BB * EH];              // context
__device__ float g_projP[2][KP * BB];         // h2.fcdW partial per d-half
__device__ float g_pdfP[2][KP * BB];          // h2.pdfW partial per d-half
__device__ int   g_srcH[KP * BB];             // composed resample index for h
__device__ int   g_srcC[KP * BB];             // resample index for c (unsorted!)
__device__ unsigned g_flag[BB];               // attention-done flag (monotonic t+1)

__device__ __forceinline__ float sigm(float x) { return 1.0f / (1.0f + expf(-x)); }
__device__ __forceinline__ float softplusf(float x) {
    return fmaxf(x, 0.0f) + log1pf(expf(-fabsf(x)));
}
__device__ __forceinline__ void fma2(ull& d, ull a, ull b) {
    asm("fma.rn.f32x2 %0, %1, %2, %0;" : "+l"(d) : "l"(a), "l"(b));
}
__device__ __forceinline__ float2 unpk(ull v) {
    float2 f; asm("mov.b64 {%0,%1}, %2;" : "=f"(f.x), "=f"(f.y) : "l"(v)); return f;
}
__device__ __forceinline__ ull pk(float lo, float hi) {
    ull u; asm("mov.b64 %0, {%1,%2};" : "=l"(u) : "f"(lo), "f"(hi)); return u;
}
__device__ __forceinline__ uint32_t s2u32(const void* p) {
    uint32_t a;
    asm("{ .reg .u64 t; cvta.to.shared.u64 t, %1; cvt.u32.u64 %0, t; }" : "=r"(a) : "l"(p));
    return a;
}
__device__ __forceinline__ void cp16(uint32_t dst, const void* src) {
    asm volatile("cp.async.ca.shared.global [%0], [%1], 16;" :: "r"(dst), "l"(src));
}
#define CP_COMMIT() asm volatile("cp.async.commit_group;")
#define CP_WAIT0()  asm volatile("cp.async.wait_group 0;")
#define CP_WAIT1()  asm volatile("cp.async.wait_group 1;")

// ---------------- dynamic smem layouts -------------------------------------
struct __align__(16) SmemG {                   // GEMM CTA
    float ws[2][8 * 256];      // 16KB W_hh chunk double buffer
    ull   h2[KP * 128];        // 32KB (h,h) pairs, k-major [k][j]
    float red_p[KP][2], red_q[KP][2];
};
struct __align__(16) SmemT {                   // attention CTA (4 groups)
    int   idxH[4][32], idxC[4][32];
    float hb[4][128], cb[4][128], hcp[4][128];
    float a_s[4][32], beta[4][32], ctx[4][128];
    float yt[4];
};

// ---------------- K0: E1 precompute + flag reset ---------------------------
__global__ void k0_e1(const float* __restrict__ enc, const float* __restrict__ W1,
                      const float* __restrict__ b1)
{
    int b = blockIdx.x, tid = threadIdx.x;
    __shared__ float enc_s[TT * EH];
    __shared__ float w1_s[16 * 128];
    if (tid == 0) g_flag[b] = 0u;
    for (int idx = tid; idx < TT * EH; idx += 256)
        enc_s[idx] = enc[b * TT * EH + idx];
    int tq = tid >> 7;
    int h  = tid & 127;
    float acc[16];
#pragma unroll
    for (int i = 0; i < 16; i++) acc[i] = 0.0f;
    for (int ec = 0; ec < 8; ec++) {
        __syncthreads();
        for (int idx = tid; idx < 16 * 128; idx += 256)
            w1_s[idx] = W1[(256 + ec * 16) * 128 + idx];
        __syncthreads();
#pragma unroll 4
        for (int jj = 0; jj < 16; jj++) {
            float wv = w1_s[jj * 128 + h];
            int e = ec * 16 + jj;
#pragma unroll
            for (int i = 0; i < 16; i++)
                acc[i] += enc_s[(tq * 16 + i) * 128 + e] * wv;
        }
    }
    float bv = b1[h];
#pragma unroll
    for (int i = 0; i < 16; i++)
        g_E1[(b * TT + tq * 16 + i) * 128 + h] = acc[i] + bv;
}

// ---------------- kStep: heterogeneous (attn CTAs + GEMM CTAs) -------------
// grid 576: bid<64  -> attention for b = bid*4 .. bid*4+3 (64 threads each)
//           bid>=64 -> GEMM: gb=bid-64, b=gb>>1, dh=gb&1
__global__ void __launch_bounds__(256, 4) kStep(
        int t, const float* __restrict__ enc, const float* __restrict__ yprev,
        const float* __restrict__ W1, const float* __restrict__ W2,
        const float* __restrict__ b2, const float* __restrict__ fcW,
        const float* __restrict__ fcb, const float* __restrict__ varW,
        const float* __restrict__ varb,
        const float* __restrict__ Whh, const float* __restrict__ Wih,
        const float* __restrict__ bih, const float* __restrict__ bhh,
        const float* __restrict__ eps,
        const float* __restrict__ fcdW, const float* __restrict__ pdfW)
{
    extern __shared__ char smem_raw[];
    int bid = blockIdx.x;
    int tid = threadIdx.x;
    int rb = (t - 1) & 1, wb = t & 1;

    if (bid < 64) {
        // ================= ATTENTION CTA =================
        SmemT* S = (SmemT*)smem_raw;
        int grp = tid >> 6, gtid = tid & 63;
        int b = bid * 4 + grp;

        // cache resample indices
        if (t > 0) {
            if (tid < 128) {
                int g2 = tid >> 5, p = tid & 31;
                S->idxH[g2][p] = g_srcH[p * BB + bid * 4 + g2];
            } else {
                int g2 = (tid - 128) >> 5, p = tid & 31;
                S->idxC[g2][p] = g_srcC[p * BB + bid * 4 + g2];
            }
        }
        __syncthreads();

        // hbar/cbar (2 d-cols per thread)
#pragma unroll
        for (int half = 0; half < 2; half++) {
            int d = gtid + half * 64;
            float sh = 0.0f, sc = 0.0f;
            if (t > 0) {
#pragma unroll 4
                for (int p = 0; p < KP; p++) {
                    sh += g_H[rb][(S->idxH[grp][p] * BB + b) * DH + d];
                    sc += g_C[rb][(S->idxC[grp][p] * BB + b) * DH + d];
                }
            }
            S->hb[grp][d] = sh * (1.0f / 32.0f);
            S->cb[grp][d] = sc * (1.0f / 32.0f);
        }
        __syncthreads();

        // hcp[h] = hbar@W1_h + cbar@W1_c   (2 cols per thread, 8 accs)
#pragma unroll
        for (int half = 0; half < 2; half++) {
            int h = gtid + half * 64;
            float a0 = 0, a1 = 0, a2 = 0, a3 = 0;
            float c0 = 0, c1 = 0, c2 = 0, c3 = 0;
#pragma unroll 4
            for (int j = 0; j < 32; j++) {
                a0 += S->hb[grp][j]      * W1[j * 128 + h];
                a1 += S->hb[grp][j + 32] * W1[(j + 32) * 128 + h];
                a2 += S->hb[grp][j + 64] * W1[(j + 64) * 128 + h];
                a3 += S->hb[grp][j + 96] * W1[(j + 96) * 128 + h];
                c0 += S->cb[grp][j]      * W1[(128 + j) * 128 + h];
                c1 += S->cb[grp][j + 32] * W1[(160 + j) * 128 + h];
                c2 += S->cb[grp][j + 64] * W1[(192 + j) * 128 + h];
                c3 += S->cb[grp][j + 96] * W1[(224 + j) * 128 + h];
            }
            S->hcp[grp][h] = ((a0 + a1) + (a2 + a3)) + ((c0 + c1) + (c2 + c3));
        }
        __syncthreads();

        // logits: 2 warps per group, 16 t' each
        {
            int w2 = gtid >> 5, lane = gtid & 31;
            for (int q = 0; q < 16; q++) {
                int tp = w2 * 16 + q;
                const float* e1 = &g_E1[(b * TT + tp) * 128];
                float acc = 0.0f;
#pragma unroll
                for (int s = 0; s < 4; s++) {
                    int hh = lane + s * 32;
                    acc += tanhf(S->hcp[grp][hh] + e1[hh]) * W2[hh];
                }
                for (int off = 16; off; off >>= 1)
                    acc += __shfl_down_sync(0xffffffffu, acc, off);
                if (lane == 0) S->a_s[grp][tp] = acc + b2[0];
            }
        }
        __syncthreads();

        // softmax over T (warp 0 of each group)
        if (gtid < 32) {
            float v = S->a_s[grp][gtid];
            float m = v;
            for (int off = 16; off; off >>= 1) m = fmaxf(m, __shfl_xor_sync(0xffffffffu, m, off));
            float e = expf(v - m);
            float s = e;
            for (int off = 16; off; off >>= 1) s += __shfl_xor_sync(0xffffffffu, s, off);
            S->beta[grp][gtid] = e / s;
        }
        __syncthreads();

        // context (2 e-cols per thread)
#pragma unroll
        for (int half = 0; half < 2; half++) {
            int e = gtid + half * 64;
            float a0 = 0, a1 = 0, a2 = 0, a3 = 0;
#pragma unroll 4
            for (int tp = 0; tp < 8; tp++) {
                a0 += S->beta[grp][tp]      * enc[(b * TT + tp) * 128 + e];
                a1 += S->beta[grp][tp + 8]  * enc[(b * TT + tp + 8) * 128 + e];
                a2 += S->beta[grp][tp + 16] * enc[(b * TT + tp + 16) * 128 + e];
                a3 += S->beta[grp][tp + 24] * enc[(b * TT + tp + 24) * 128 + e];
            }
            float acc = (a0 + a1) + (a2 + a3);
            S->ctx[grp][e] = acc;
            g_ctx[b * 128 + e] = acc;
        }
        __syncthreads();

        // y_tilde (warp 0 of group)
        if (gtid < 32) {
            float acc = 0.0f;
#pragma unroll
            for (int s = 0; s < 4; s++)
                acc += S->ctx[grp][gtid + s * 32] * fcW[gtid + s * 32];
            for (int off = 16; off; off >>= 1)
                acc += __shfl_down_sync(0xffffffffu, acc, off);
            if (gtid == 0) {
                float yt = acc + yprev[b * TT + t] * fcW[128] + fcb[0];
                S->yt[grp] = yt;
                g_yt[b] = yt;
            }
        }
        __syncthreads();

        // var -> softplus (2 d-cols per thread)
#pragma unroll
        for (int half = 0; half < 2; half++) {
            int d = gtid + half * 64;
            float a0 = 0, a1 = 0, a2 = 0, a3 = 0;
#pragma unroll 4
            for (int j = 0; j < 32; j++) {
                a0 += S->hb[grp][j]      * varW[(1 + j) * 128 + d];
                a1 += S->hb[grp][j + 32] * varW[(33 + j) * 128 + d];
                a2 += S->hb[grp][j + 64] * varW[(65 + j) * 128 + d];
                a3 += S->hb[grp][j + 96] * varW[(97 + j) * 128 + d];
            }
            float v = (a0 + a1) + (a2 + a3) + S->yt[grp] * varW[d] + varb[d];
            g_spF[b * 128 + d] = softplusf(v);
        }
        __threadfence();
        __syncthreads();
        if (tid < 4) atomicExch(&g_flag[bid * 4 + tid], (unsigned)(t + 1));
        return;
    }

    // ================= GEMM CTA =================
    SmemG* S = (SmemG*)smem_raw;
    int gb = bid - 64;
    int b = gb >> 1, dh = gb & 1;
    int dhoff = dh * 64;

    // cp.async prologue: W_hh chunks 0,1
    if (t > 0) {
#pragma unroll
        for (int c0 = 0; c0 < 2; c0++) {
            uint32_t dstb = s2u32(&S->ws[c0][0]);
#pragma unroll
            for (int n = 0; n < 2; n++) {
                int L = tid + n * 256;
                int row = L >> 6, rem = L & 63;
                int seg = rem >> 4, q = rem & 15;
                const float* src = Whh + (c0 * 8 + row) * 512 + seg * 128 + dhoff + q * 4;
                cp16(dstb + (row * 256 + seg * 64 + q * 4) * 4, src);
            }
            CP_COMMIT();
        }
        // fill h2[k][j] = (h,h) via resample gather
        for (int m = 0; m < 16; m++) {
            int idx = tid + m * 256;
            int k = idx >> 7, j = idx & 127;
            int row = g_srcH[k * BB + b];
            float hv = g_H[rb][(row * BB + b) * DH + j];
            S->h2[k * 128 + j] = pk(hv, hv);
        }
    }
    __syncthreads();

    int kg  = tid >> 5;        // 0..7 : 4 particles each; one warp per kg
    int dqh = tid & 31;        // d-pair within half
    int d0l = dqh * 2;
    int d0g = dhoff + d0l;

    ull acc2[4][4];
#pragma unroll
    for (int i = 0; i < 4; i++)
#pragma unroll
        for (int g = 0; g < 4; g++) acc2[i][g] = 0ull;

    if (t > 0) {
        for (int ch = 0; ch < 16; ch++) {
            if (ch < 15) { CP_WAIT1(); } else { CP_WAIT0(); }
            __syncthreads();
            const float* wsb = S->ws[ch & 1];
#pragma unroll
            for (int jj = 0; jj < 8; jj++) {
                int j = ch * 8 + jj;
                ull h0 = S->h2[(kg * 4 + 0) * 128 + j];
                ull h1 = S->h2[(kg * 4 + 1) * 128 + j];
                ull h2v = S->h2[(kg * 4 + 2) * 128 + j];
                ull h3 = S->h2[(kg * 4 + 3) * 128 + j];
                const ull* wp = (const ull*)(wsb + jj * 256);
                ull w0 = wp[dqh], w1 = wp[32 + dqh], w2 = wp[64 + dqh], w3 = wp[96 + dqh];
                fma2(acc2[0][0], h0, w0); fma2(acc2[0][1], h0, w1);
                fma2(acc2[0][2], h0, w2); fma2(acc2[0][3], h0, w3);
                fma2(acc2[1][0], h1, w0); fma2(acc2[1][1], h1, w1);
                fma2(acc2[1][2], h1, w2); fma2(acc2[1][3], h1, w3);
                fma2(acc2[2][0], h2v, w0); fma2(acc2[2][1], h2v, w1);
                fma2(acc2[2][2], h2v, w2); fma2(acc2[2][3], h2v, w3);
                fma2(acc2[3][0], h3, w0); fma2(acc2[3][1], h3, w1);
                fma2(acc2[3][2], h3, w2); fma2(acc2[3][3], h3, w3);
            }
            __syncthreads();
            if (ch + 2 < 16) {
                uint32_t dstb = s2u32(&S->ws[ch & 1][0]);
#pragma unroll
                for (int n = 0; n < 2; n++) {
                    int L = tid + n * 256;
                    int row = L >> 6, rem = L & 63;
                    int seg = rem >> 4, q = rem & 15;
                    const float* src = Whh + ((ch + 2) * 8 + row) * 512 + seg * 128 + dhoff + q * 4;
                    cp16(dstb + (row * 256 + seg * 64 + q * 4) * 4, src);
                }
                CP_COMMIT();
            }
        }
    }

    // wait for attention results (producer CTAs run concurrently)
    if (tid == 0) {
        while (atomicAdd(&g_flag[b], 0u) < (unsigned)(t + 1)) { }
    }
    __syncthreads();

    // ---- epilogue: gates -> c2/h2, reparam, dots ----
    float yt = g_yt[b];
    float2 spv = *(const float2*)&g_spF[b * 128 + d0g];

    float xb[8];
#pragma unroll
    for (int g4 = 0; g4 < 4; g4++)
#pragma unroll
        for (int dd = 0; dd < 2; dd++) {
            int col = g4 * 128 + d0g + dd;
            xb[g4 * 2 + dd] = yt * Wih[col] + bih[col] + bhh[col];
        }

    float fcd0 = fcdW[d0g], fcd1 = fcdW[d0g + 1];
    float pw0 = pdfW[d0g],  pw1 = pdfW[d0g + 1];
    float pacc[4], qacc[4];
#pragma unroll
    for (int i = 0; i < 4; i++) {
        int k = kg * 4 + i;
        float2 gi = unpk(acc2[i][0]);
        float2 gf = unpk(acc2[i][1]);
        float2 gg = unpk(acc2[i][2]);
        float2 go = unpk(acc2[i][3]);
        float cp0 = 0.0f, cp1 = 0.0f;
        if (t > 0) {
            int crow = g_srcC[k * BB + b];
            float2 cv = *(const float2*)&g_C[rb][(crow * BB + b) * DH + d0g];
            cp0 = cv.x; cp1 = cv.y;
        }
        float ii0 = gi.x + xb[0], ii1 = gi.y + xb[1];
        float ff0 = gf.x + xb[2], ff1 = gf.y + xb[3];
        float gg0 = gg.x + xb[4], gg1 = gg.y + xb[5];
        float oo0 = go.x + xb[6], oo1 = go.y + xb[7];
        float c20 = sigm(ff0) * cp0 + sigm(ii0) * tanhf(gg0);
        float c21 = sigm(ff1) * cp1 + sigm(ii1) * tanhf(gg1);
        float h20 = sigm(oo0) * tanhf(c20);
        float h21 = sigm(oo1) * tanhf(c21);
        float2 ev = *(const float2*)&eps[(((size_t)t * KP + k) * BB + b) * DH + d0g];
        h20 += ev.x * spv.x;
        h21 += ev.y * spv.y;
        int o = (k * BB + b) * DH + d0g;
        *(float2*)&g_H[wb][o] = make_float2(h20, h21);
        *(float2*)&g_C[wb][o] = make_float2(c20, c21);
        pacc[i] = h20 * fcd0 + h21 * fcd1;
        qacc[i] = h20 * pw0 + h21 * pw1;
    }
#pragma unroll
    for (int i = 0; i < 4; i++) {
        float p = pacc[i], q = qacc[i];
        for (int off = 16; off; off >>= 1) {
            p += __shfl_down_sync(0xffffffffu, p, off);
            q += __shfl_down_sync(0xffffffffu, q, off);
        }
        if (dqh == 0) {
            int k = kg * 4 + i;
            g_projP[dh][k * BB + b] = p;
            g_pdfP[dh][k * BB + b] = q;
        }
    }
}

// ---------------- K3: sort / weights / gumbel-max resample ----------------
__global__ void __launch_bounds__(1024) k3_resample(
        int t, const float* __restrict__ gumbel,
        const float* __restrict__ pdfW, const float* __restrict__ pdfb,
        const float* __restrict__ fcdb)
{
    int blk = blockIdx.x;          // 0..7 (32-b normalization groups)
    int tid = threadIdx.x;         // 1024
    __shared__ float proj_s[32][33];
    __shared__ int   order_s[32][33];
    __shared__ float pd_s[32][33];
    __shared__ float lw_s[32][33];

    {
        int kk = tid >> 5, bb = tid & 31;
        int gi = kk * BB + blk * 32 + bb;
        proj_s[bb][kk] = g_projP[0][gi] + g_projP[1][gi] + fcdb[0];
        pd_s[bb][kk]   = g_pdfP[0][gi] + g_pdfP[1][gi];
    }
    __syncthreads();
    {   // stable ascending rank (matches jnp.argsort)
        int bl = tid >> 5, k = tid & 31;
        float v = proj_s[bl][k];
        int r = 0;
#pragma unroll
        for (int kp = 0; kp < 32; kp++) {
            float u = proj_s[bl][kp];
            r += (u < v) || (u == v && kp < k);
        }
        order_s[bl][r] = k;
    }
    __syncthreads();
    {
        int slot = tid >> 5, bb = tid & 31;
        int bg = blk * 32 + bb;
        int k0 = order_s[bb][slot];
        float lp = pd_s[bb][k0] + g_yt[bg] * pdfW[128] + pdfb[0];
        float v = expf(lp);
        float s = v;
        for (int off = 16; off; off >>= 1) s += __shfl_xor_sync(0xffffffffu, s, off);
        lw_s[bb][slot] = logf(v / s + 1e-30f);
    }
    __syncthreads();
    {
        int p = tid >> 5, lane = tid & 31;
        const float* gbase = &gumbel[(((size_t)t * BB + blk * 32) * KP + p) * KP + lane];
        float gv[32];
#pragma unroll
        for (int it = 0; it < 32; it++)
            gv[it] = gbase[(size_t)it * KP * KP];
#pragma unroll
        for (int it = 0; it < 32; it++) {
            float v = lw_s[it][lane] + gv[it];
            int bi = lane;
            for (int off = 16; off; off >>= 1) {
                float ov = __shfl_down_sync(0xffffffffu, v, off);
                int  obi = __shfl_down_sync(0xffffffffu, bi, off);
                if (ov > v || (ov == v && obi < bi)) { v = ov; bi = obi; }
            }
            if (lane == 0) {
                int bg = blk * 32 + it;
                g_srcH[p * BB + bg] = order_s[it][bi];
                g_srcC[p * BB + bg] = bi;
            }
        }
    }
}

// ---------------- K4: final projections -----------------------------------
__global__ void k4_out(const float* __restrict__ fcdW, const float* __restrict__ fcdb,
                       const float* __restrict__ fceW, const float* __restrict__ fceb,
                       float* __restrict__ out)
{
    int b = blockIdx.x * 8 + (threadIdx.x >> 5);
    int lane = threadIdx.x & 31;
    float a1 = 0.0f, a2 = 0.0f;
    for (int d = lane; d < 128; d += 32) {
        float hm = 0.0f;
        for (int p = 0; p < KP; p++) {
            int row = g_srcH[p * BB + b];
            hm += g_H[1][(row * BB + b) * DH + d];   // (T-1)&1 == 1
        }
        a1 += (hm * (1.0f / 32.0f)) * fcdW[d];
        a2 += g_ctx[b * 128 + d] * fceW[d];
    }
    for (int off = 16; off; off >>= 1) {
        a1 += __shfl_down_sync(0xffffffffu, a1, off);
        a2 += __shfl_down_sync(0xffffffffu, a2, off);
    }
    if (lane == 0) out[b] = a1 + fcdb[0] + a2 + fceb[0];
}

// ---------------- launch ---------------------------------------------------
extern "C" void kernel_launch(void* const* d_in, const int* in_sizes, int n_in,
                              void* d_out, int out_size)
{
    const float* enc   = (const float*)d_in[0];
    const float* yprev = (const float*)d_in[1];
    const float* eps   = (const float*)d_in[2];
    const float* gum   = (const float*)d_in[3];
    const float* W1    = (const float*)d_in[4];
    const float* b1    = (const float*)d_in[5];
    const float* W2    = (const float*)d_in[6];
    const float* b2    = (const float*)d_in[7];
    const float* Wih   = (const float*)d_in[8];
    const float* Whh   = (const float*)d_in[9];
    const float* bih   = (const float*)d_in[10];
    const float* bhh   = (const float*)d_in[11];
    const float* fcW   = (const float*)d_in[12];
    const float* fcb   = (const float*)d_in[13];
    const float* fcdW  = (const float*)d_in[14];
    const float* fcdb  = (const float*)d_in[15];
    const float* fceW  = (const float*)d_in[16];
    const float* fceb  = (const float*)d_in[17];
    const float* varW  = (const float*)d_in[18];
    const float* varb  = (const float*)d_in[19];
    const float* pdfW  = (const float*)d_in[20];
    const float* pdfb  = (const float*)d_in[21];
    float* out = (float*)d_out;

    int smem = (int)sizeof(SmemG);
    if ((int)sizeof(SmemT) > smem) smem = (int)sizeof(SmemT);
    cudaFuncSetAttribute(kStep, cudaFuncAttributeMaxDynamicSharedMemorySize, smem);

    k0_e1<<<BB, 256>>>(enc, W1, b1);
    for (int t = 0; t < TT; t++) {
        kStep<<<64 + BB * 2, 256, smem>>>(t, enc, yprev, W1, W2, b2, fcW, fcb,
                                          varW, varb, Whh, Wih, bih, bhh, eps,
                                          fcdW, pdfW);
        k3_resample<<<8, 1024>>>(t, gum, pdfW, pdfb, fcdb);
    }
    k4_out<<<BB / 8, 256>>>(fcdW, fcdb, fceW, fceb, out);
}